// round 10
// baseline (speedup 1.0000x reference)
#include <cuda_runtime.h>
#include <cuda_fp16.h>
#include <cstdint>
#include <math.h>

#define N_ROWS 16384
#define DDIM   4096
#define NEXP   256
#define KTOP   6

#define BM 64             // rows per CTA
#define BK 32             // k per A-stage (two k16 steps)
#define NIT (DDIM / BK)   // 128
#define NTHREADS 256      // 8 warps: 2 (m) x 4 (n), warp tile 32x64
#define LO_SCALE 2048.0f
#define LO_UNSCALE 4.8828125e-4f   // 2^-11

// ---- smem layout (dynamic) ----
#define SM_BIAS    0
#define SM_STAGE   1024          // 2 A-stages of 8KB (hi 4K + lo 4K)
#define STAGE_BYTES 8192
#define A_LVL 4096
// post-mainloop overlay:
#define SSTR 260
#define SM_SCORES  1024                                    // 64*260*4 = 66560
#define SM_PB (SM_SCORES + BM * SSTR * 4)                  // 67584
#define SM_PO (SM_PB + BM * 4 * KTOP * 4)                  // +6144
#define SM_PI (SM_PO + BM * 4 * KTOP * 4)                  // +6144 -> 86016... wait see below
#define SM_MST (SM_PI + BM * 4 * KTOP * 4)                 // masters (alive whole kernel)
#define SMEM_TOTAL (SM_MST + 64 * NTHREADS * 4)            // 151552

// B in mma-fragment order: per k16 "kt" a 16KB block:
//   [lvl(2)][n16-group(16)] x 512B, lane l's uint4 at l*16.
//   uint4 = { pack(B[k0][nE],B[k0+1][nE]), pack(B[k0+8][nE],B[k0+9][nE]),
//             pack(B[k0][nO],B[k0+1][nO]), pack(B[k0+8][nO],B[k0+9][nO]) }
//   nE = g*16 + l/4, nO = nE + 8, k0 = kt*16 + (l%4)*2.
// One extra kt block so the tail prefetch never reads unmapped memory.
__device__ __align__(16) uint8_t g_bfrag[(size_t)257 * 16384];

// ---------------------------------------------------------------------------
static __device__ __forceinline__ uint32_t smem_u32(const void* p) {
    uint32_t a;
    asm("{ .reg .u64 t; cvta.to.shared.u64 t, %1; cvt.u32.u64 %0, t; }" : "=r"(a) : "l"(p));
    return a;
}

static __device__ __forceinline__ void sts_u2(uint32_t addr, uint2 v) {
    asm volatile("st.shared.v2.b32 [%0], {%1, %2};"
                 :: "r"(addr), "r"(v.x), "r"(v.y) : "memory");
}

static __device__ __forceinline__ uint32_t pack_h2(__half lo, __half hi) {
    return (uint32_t)__half_as_ushort(lo) | ((uint32_t)__half_as_ushort(hi) << 16);
}

static __device__ __forceinline__ void split1(float a, __half& h, __half& l) {
    h = __float2half_rn(a);
    l = __float2half_rn((a - __half2float(h)) * LO_SCALE);
}

// split fp32x4 into fp16 hi + fp16 lo*2^11
static __device__ __forceinline__ void split2_f4(float4 v, uint2& h, uint2& l) {
    __half h0, l0, h1, l1, h2, l2, h3, l3;
    split1(v.x, h0, l0); split1(v.y, h1, l1);
    split1(v.z, h2, l2); split1(v.w, h3, l3);
    h = make_uint2(pack_h2(h0, h1), pack_h2(h2, h3));
    l = make_uint2(pack_h2(l0, l1), pack_h2(l2, l3));
}

static __device__ __forceinline__ void ldsm4(uint32_t* r, uint32_t addr) {
    asm volatile("ldmatrix.sync.aligned.m8n8.x4.shared.b16 {%0,%1,%2,%3}, [%4];"
                 : "=r"(r[0]), "=r"(r[1]), "=r"(r[2]), "=r"(r[3]) : "r"(addr));
}

// non-volatile — pure register computation, lets the compiler interleave
static __device__ __forceinline__ void mma_f16(float* d, const uint32_t* a,
                                               uint32_t b0, uint32_t b1) {
    asm("mma.sync.aligned.m16n8k16.row.col.f32.f16.f16.f32 "
        "{%0,%1,%2,%3}, {%4,%5,%6,%7}, {%8,%9}, {%0,%1,%2,%3};"
        : "+f"(d[0]), "+f"(d[1]), "+f"(d[2]), "+f"(d[3])
        : "r"(a[0]), "r"(a[1]), "r"(a[2]), "r"(a[3]), "r"(b0), "r"(b1));
}

// 64B-row swizzle for A staging
static __device__ __forceinline__ uint32_t row64_addr(uint32_t base, int row, int lchunk) {
    return base + row * 64 + ((lchunk ^ ((row >> 1) & 3)) << 4);
}

// stable strict-> insertion into top-6 (earlier insert wins ties = lower index)
static __device__ __forceinline__ void ins6(float b, float o, int idx,
                                            float* tb, float* to_, int* ti) {
    if (b > tb[KTOP - 1]) {
        int p = KTOP - 1;
#pragma unroll
        for (int q = KTOP - 1; q > 0; q--) {
            if (b > tb[q - 1]) {
                tb[q] = tb[q - 1]; to_[q] = to_[q - 1]; ti[q] = ti[q - 1];
                p = q - 1;
            }
        }
        tb[p] = b; to_[p] = o; ti[p] = idx;
    }
}

// ---------------------------------------------------------------------------
// Pre-kernel: write B in mma-fragment order (see g_bfrag comment).
// 131072 threads, one 32B output (2 uint4) each.
// ---------------------------------------------------------------------------
__global__ __launch_bounds__(256) void preconvert_B(const float* __restrict__ B) {
    int t = blockIdx.x * 256 + threadIdx.x;   // 0..131071
    int lane = t & 31;
    int g    = (t >> 5) & 15;
    int kt   = t >> 9;                        // 0..255
    int nE = g * 16 + (lane >> 2);
    int nO = nE + 8;
    int k0 = kt * 16 + (lane & 3) * 2;

    const float* rE = B + (size_t)nE * DDIM;
    const float* rO = B + (size_t)nO * DDIM;
    float e0 = rE[k0], e1 = rE[k0 + 1], e8 = rE[k0 + 8], e9 = rE[k0 + 9];
    float o0 = rO[k0], o1 = rO[k0 + 1], o8 = rO[k0 + 8], o9 = rO[k0 + 9];

    __half h, l;
    uint4 H, L;
    __half he0,le0,he1,le1,he8,le8,he9,le9, ho0,lo0,ho1,lo1,ho8,lo8,ho9,lo9;
    split1(e0,he0,le0); split1(e1,he1,le1); split1(e8,he8,le8); split1(e9,he9,le9);
    split1(o0,ho0,lo0); split1(o1,ho1,lo1); split1(o8,ho8,lo8); split1(o9,ho9,lo9);
    H = make_uint4(pack_h2(he0,he1), pack_h2(he8,he9), pack_h2(ho0,ho1), pack_h2(ho8,ho9));
    L = make_uint4(pack_h2(le0,le1), pack_h2(le8,le9), pack_h2(lo0,lo1), pack_h2(lo8,lo9));

    uint8_t* dst = g_bfrag + (size_t)kt * 16384 + g * 512 + lane * 16;
    *reinterpret_cast<uint4*>(dst)        = H;      // lvl 0 (hi)
    *reinterpret_cast<uint4*>(dst + 8192) = L;      // lvl 1 (lo)
}

// ---------------------------------------------------------------------------
// Fused main kernel: fp16x2 HMMA GEMM + sqrt-softplus + stable top-6.
// B fragments come straight from L2 via LDG.128 (fragment-order gmem),
// double-buffered in registers across k16 steps — no B smem, no B ldsm.
// A staged in smem (8KB ping-pong), 4 ldsm per warp-k16.
// acc0 = hi*hi (chunk-folded into smem masters every K=256);
// acc1 = cross terms (scaled 2^11, folded once at the end * 2^-11).
// ---------------------------------------------------------------------------
__global__ __launch_bounds__(NTHREADS, 1) void gate_main(
    const float* __restrict__ A, const float* __restrict__ bias,
    float* __restrict__ out) {
    extern __shared__ char smem[];
    const int tid  = threadIdx.x;
    const int lane = tid & 31;
    const int wid  = tid >> 5;
    const int wm   = wid >> 2;          // 0..1
    const int wn   = wid & 3;           // 0..3
    const int mBase = blockIdx.x * BM;
    float* s_bias = reinterpret_cast<float*>(smem + SM_BIAS);
    float* s_mst  = reinterpret_cast<float*>(smem + SM_MST);

    if (tid < NEXP) s_bias[tid] = bias[tid];

    const int g  = lane >> 3;           // ldmatrix lane group
    const int l7 = lane & 7;

    float acc0[2][8][4], acc1[2][8][4];
#pragma unroll
    for (int mf = 0; mf < 2; mf++)
#pragma unroll
        for (int j = 0; j < 8; j++)
#pragma unroll
            for (int c = 0; c < 4; c++) { acc0[mf][j][c] = 0.0f; acc1[mf][j][c] = 0.0f; }

    const uint32_t sbase = smem_u32(smem) + SM_STAGE;

    // per-warp B fragment pointer: + kt*16384 + lvl*8192 + nf2*512
    const char* bwarp = (const char*)g_bfrag + wn * 2048 + lane * 16;

    // ---- prologue: A stage 0, preload B frags for kt=0 ----
#pragma unroll
    for (int s = 0; s < 2; s++) {
        int task = s * NTHREADS + tid;
        int row = task >> 3, kg = task & 7;
        float4 v = *reinterpret_cast<const float4*>(
            &A[(size_t)(mBase + row) * DDIM + kg * 4]);
        uint2 h, l;
        split2_f4(v, h, l);
        int lchunk = kg >> 1, half = (kg & 1) * 8;
        sts_u2(row64_addr(sbase, row, lchunk) + half, h);
        sts_u2(row64_addr(sbase + A_LVL, row, lchunk) + half, l);
    }

    uint4 bAh[4], bAl[4], bBh[4], bBl[4];
#pragma unroll
    for (int nf2 = 0; nf2 < 4; nf2++) {
        bAh[nf2] = *reinterpret_cast<const uint4*>(bwarp + nf2 * 512);
        bAl[nf2] = *reinterpret_cast<const uint4*>(bwarp + 8192 + nf2 * 512);
    }
    const char* bpn = bwarp + 16384;    // next prefetch: kt=1
    __syncthreads();

#pragma unroll 1
    for (int it = 0; it < NIT; it++) {
        const uint32_t stage  = sbase + (it & 1) * STAGE_BYTES;
        const uint32_t nstage = sbase + ((it + 1) & 1) * STAGE_BYTES;

        float4 areg[2];
        if (it + 1 < NIT) {
#pragma unroll
            for (int s = 0; s < 2; s++) {
                int task = s * NTHREADS + tid;
                int row = task >> 3, kg = task & 7;
                areg[s] = *reinterpret_cast<const float4*>(
                    &A[(size_t)(mBase + row) * DDIM + (it + 1) * BK + kg * 4]);
            }
        }

        // ======== k16 step 0 (kt = 2*it): use bA, prefetch into bB ========
        {
            uint32_t ah[2][4], al[2][4];
#pragma unroll
            for (int mf = 0; mf < 2; mf++) {
                int row = wm * 32 + mf * 16 + (g & 1) * 8 + l7;
                int lchunk = 0 * 2 + (g >> 1);
                ldsm4(ah[mf], row64_addr(stage, row, lchunk));
                ldsm4(al[mf], row64_addr(stage + A_LVL, row, lchunk));
            }
#pragma unroll
            for (int nf2 = 0; nf2 < 4; nf2++) {
                bBh[nf2] = *reinterpret_cast<const uint4*>(bpn + nf2 * 512);
                bBl[nf2] = *reinterpret_cast<const uint4*>(bpn + 8192 + nf2 * 512);
            }
            bpn += 16384;
#pragma unroll
            for (int nf2 = 0; nf2 < 4; nf2++) {
#pragma unroll
                for (int mf = 0; mf < 2; mf++) {
                    mma_f16(acc0[mf][nf2 * 2 + 0], ah[mf], bAh[nf2].x, bAh[nf2].y);
                    mma_f16(acc0[mf][nf2 * 2 + 1], ah[mf], bAh[nf2].z, bAh[nf2].w);
                    mma_f16(acc1[mf][nf2 * 2 + 0], ah[mf], bAl[nf2].x, bAl[nf2].y);
                    mma_f16(acc1[mf][nf2 * 2 + 1], ah[mf], bAl[nf2].z, bAl[nf2].w);
                    mma_f16(acc1[mf][nf2 * 2 + 0], al[mf], bAh[nf2].x, bAh[nf2].y);
                    mma_f16(acc1[mf][nf2 * 2 + 1], al[mf], bAh[nf2].z, bAh[nf2].w);
                }
            }
        }

        // ======== k16 step 1 (kt = 2*it+1): use bB, prefetch into bA ========
        {
            uint32_t ah[2][4], al[2][4];
#pragma unroll
            for (int mf = 0; mf < 2; mf++) {
                int row = wm * 32 + mf * 16 + (g & 1) * 8 + l7;
                int lchunk = 1 * 2 + (g >> 1);
                ldsm4(ah[mf], row64_addr(stage, row, lchunk));
                ldsm4(al[mf], row64_addr(stage + A_LVL, row, lchunk));
            }
#pragma unroll
            for (int nf2 = 0; nf2 < 4; nf2++) {
                bAh[nf2] = *reinterpret_cast<const uint4*>(bpn + nf2 * 512);
                bAl[nf2] = *reinterpret_cast<const uint4*>(bpn + 8192 + nf2 * 512);
            }
            bpn += 16384;
#pragma unroll
            for (int nf2 = 0; nf2 < 4; nf2++) {
#pragma unroll
                for (int mf = 0; mf < 2; mf++) {
                    mma_f16(acc0[mf][nf2 * 2 + 0], ah[mf], bBh[nf2].x, bBh[nf2].y);
                    mma_f16(acc0[mf][nf2 * 2 + 1], ah[mf], bBh[nf2].z, bBh[nf2].w);
                    mma_f16(acc1[mf][nf2 * 2 + 0], ah[mf], bBl[nf2].x, bBl[nf2].y);
                    mma_f16(acc1[mf][nf2 * 2 + 1], ah[mf], bBl[nf2].z, bBl[nf2].w);
                    mma_f16(acc1[mf][nf2 * 2 + 0], al[mf], bBh[nf2].x, bBh[nf2].y);
                    mma_f16(acc1[mf][nf2 * 2 + 1], al[mf], bBh[nf2].z, bBh[nf2].w);
                }
            }
        }

        if (it + 1 < NIT) {
#pragma unroll
            for (int s = 0; s < 2; s++) {
                int task = s * NTHREADS + tid;
                int row = task >> 3, kg = task & 7;
                uint2 h, l;
                split2_f4(areg[s], h, l);
                int lchunk = kg >> 1, half = (kg & 1) * 8;
                sts_u2(row64_addr(nstage, row, lchunk) + half, h);
                sts_u2(row64_addr(nstage + A_LVL, row, lchunk) + half, l);
            }
        }

        // fold hi*hi chunk into smem masters every 8 iterations (K chunk = 256)
        if ((it & 7) == 7) {
            if (it == 7) {
#pragma unroll
                for (int mf = 0; mf < 2; mf++)
#pragma unroll
                    for (int j = 0; j < 8; j++)
#pragma unroll
                        for (int c = 0; c < 4; c++) {
                            s_mst[((mf * 8 + j) * 4 + c) * NTHREADS + tid] = acc0[mf][j][c];
                            acc0[mf][j][c] = 0.0f;
                        }
            } else {
#pragma unroll
                for (int mf = 0; mf < 2; mf++)
#pragma unroll
                    for (int j = 0; j < 8; j++)
#pragma unroll
                        for (int c = 0; c < 4; c++) {
                            s_mst[((mf * 8 + j) * 4 + c) * NTHREADS + tid] += acc0[mf][j][c];
                            acc0[mf][j][c] = 0.0f;
                        }
            }
        }

        __syncthreads();
    }

    // ---- write scores to smem (overlay A stages): score = mst + acc1*2^-11 ----
    float* sc = reinterpret_cast<float*>(smem + SM_SCORES);
#pragma unroll
    for (int mf = 0; mf < 2; mf++) {
#pragma unroll
        for (int nf = 0; nf < 8; nf++) {
            int m0 = wm * 32 + mf * 16 + (lane >> 2);
            int n0 = wn * 64 + nf * 8 + (lane & 3) * 2;
            int jb = (mf * 8 + nf) * 4;
            float s0 = s_mst[(jb + 0) * NTHREADS + tid] + acc1[mf][nf][0] * LO_UNSCALE;
            float s1 = s_mst[(jb + 1) * NTHREADS + tid] + acc1[mf][nf][1] * LO_UNSCALE;
            float s2 = s_mst[(jb + 2) * NTHREADS + tid] + acc1[mf][nf][2] * LO_UNSCALE;
            float s3 = s_mst[(jb + 3) * NTHREADS + tid] + acc1[mf][nf][3] * LO_UNSCALE;
            *reinterpret_cast<float2*>(&sc[m0 * SSTR + n0]) = make_float2(s0, s1);
            *reinterpret_cast<float2*>(&sc[(m0 + 8) * SSTR + n0]) = make_float2(s2, s3);
        }
    }
    __syncthreads();

    // ---- top-6: 4 threads per row, each scans 64 experts, then merge ----
    {
        const int r = tid >> 2;     // row 0..63
        const int q = tid & 3;      // quarter
        float tb[KTOP], to_[KTOP];
        int ti[KTOP];
#pragma unroll
        for (int i = 0; i < KTOP; i++) { tb[i] = -1e30f; to_[i] = 0.0f; ti[i] = 0; }
#pragma unroll 4
        for (int j = 0; j < 64; j++) {
            int e = q * 64 + j;
            float z = sc[r * SSTR + e];
            float sp = fmaxf(z, 0.0f) + log1pf(expf(-fabsf(z)));
            float o = sqrtf(sp);
            ins6(o + s_bias[e], o, e, tb, to_, ti);
        }
        float* pb = reinterpret_cast<float*>(smem + SM_PB);
        float* po = reinterpret_cast<float*>(smem + SM_PO);
        int*   pi = reinterpret_cast<int*>(smem + SM_PI);
#pragma unroll
        for (int i = 0; i < KTOP; i++) {
            pb[(r * 4 + q) * KTOP + i] = tb[i];
            po[(r * 4 + q) * KTOP + i] = to_[i];
            pi[(r * 4 + q) * KTOP + i] = ti[i];
        }
        __syncthreads();

        if (q == 0) {
            float fb[KTOP], fo[KTOP];
            int fi[KTOP];
#pragma unroll
            for (int i = 0; i < KTOP; i++) { fb[i] = -1e30f; fo[i] = 0.0f; fi[i] = 0; }
#pragma unroll
            for (int q2 = 0; q2 < 4; q2++)
#pragma unroll
                for (int i = 0; i < KTOP; i++)
                    ins6(pb[(r * 4 + q2) * KTOP + i], po[(r * 4 + q2) * KTOP + i],
                         pi[(r * 4 + q2) * KTOP + i], fb, fo, fi);
            float sum = 0.0f;
#pragma unroll
            for (int i = 0; i < KTOP; i++) sum += fo[i];
            const float s = 1.5f / sum;
            const size_t row = (size_t)(mBase + r);
#pragma unroll
            for (int i = 0; i < KTOP; i++) {
                out[row * KTOP + i] = fo[i] * s;
                out[(size_t)N_ROWS * KTOP + row * KTOP + i] = (float)fi[i];
            }
        }
    }
}

extern "C" void kernel_launch(void* const* d_in, const int* in_sizes, int n_in,
                              void* d_out, int out_size) {
    const float* x      = (const float*)d_in[0];   // [N, D]
    const float* weight = (const float*)d_in[1];   // [E, D]
    const float* bias   = (const float*)d_in[2];   // [E]
    float* out = (float*)d_out;

    preconvert_B<<<512, 256>>>(weight);
    cudaFuncSetAttribute(gate_main, cudaFuncAttributeMaxDynamicSharedMemorySize, SMEM_TOTAL);
    gate_main<<<N_ROWS / BM, NTHREADS, SMEM_TOTAL>>>(x, bias, out);
}

// round 11
// speedup vs baseline: 1.0292x; 1.0292x over previous
#include <cuda_runtime.h>
#include <cuda_fp16.h>
#include <cstdint>
#include <math.h>

#define N_ROWS 16384
#define DDIM   4096
#define NEXP   256
#define KTOP   6

#define BM 64             // rows per CTA
#define BK 32             // k per stage (two k16 steps)
#define NIT (DDIM / BK)   // 128
#define NTHREADS 512      // 16 warps: 2 (m) x 8 (n), warp tile 32x32
#define LO_SCALE 2048.0f
#define LO_UNSCALE 4.8828125e-4f   // 2^-11

// ---- smem layout (dynamic) ----
// [0,1024): bias; 3 stages at 1024 + s*40960; mst after stages
// stage: A_h 4K | A_l 4K | B_h 16K | B_l 16K = 40K
#define SM_BIAS    0
#define SM_STAGE   1024
#define STAGE_BYTES 40960
#define A_LVL 4096
#define B_OFF 8192
#define B_LVL 16384
#define SM_MST     (SM_STAGE + 3 * STAGE_BYTES)            // 123904
#define SMEM_TOTAL (SM_MST + 32 * NTHREADS * 4)            // 189440

// scores overlay (after mainloop, over stage region)
#define SSTR 260
#define SM_SCORES  SM_STAGE
#define SM_PB (SM_SCORES + BM * SSTR * 4)
#define SM_PO (SM_PB + BM * 8 * KTOP * 4)
#define SM_PI (SM_PO + BM * 8 * KTOP * 4)

// 4 MB pre-converted, pre-swizzled B: [k32-block(128)][level(2)][n(256)][64B]
__device__ __align__(16) uint8_t g_bpre[(size_t)128 * 2 * NEXP * 64];

// ---------------------------------------------------------------------------
static __device__ __forceinline__ uint32_t smem_u32(const void* p) {
    uint32_t a;
    asm("{ .reg .u64 t; cvta.to.shared.u64 t, %1; cvt.u32.u64 %0, t; }" : "=r"(a) : "l"(p));
    return a;
}

static __device__ __forceinline__ void sts_u2(uint32_t addr, uint2 v) {
    asm volatile("st.shared.v2.b32 [%0], {%1, %2};"
                 :: "r"(addr), "r"(v.x), "r"(v.y) : "memory");
}

static __device__ __forceinline__ uint32_t pack_h2(__half lo, __half hi) {
    return (uint32_t)__half_as_ushort(lo) | ((uint32_t)__half_as_ushort(hi) << 16);
}

// split fp32x4 into fp16 hi + fp16 lo*2^11 (lo pre-scaled into normal range)
static __device__ __forceinline__ void split2_f4(float4 v, uint2& h, uint2& l) {
    float in[4] = {v.x, v.y, v.z, v.w};
    __half hh[4], hl[4];
#pragma unroll
    for (int i = 0; i < 4; i++) {
        float a = in[i];
        hh[i] = __float2half_rn(a);
        float r = a - __half2float(hh[i]);
        hl[i] = __float2half_rn(r * LO_SCALE);
    }
    h = make_uint2(pack_h2(hh[0], hh[1]), pack_h2(hh[2], hh[3]));
    l = make_uint2(pack_h2(hl[0], hl[1]), pack_h2(hl[2], hl[3]));
}

static __device__ __forceinline__ void ldsm4(uint32_t* r, uint32_t addr) {
    asm volatile("ldmatrix.sync.aligned.m8n8.x4.shared.b16 {%0,%1,%2,%3}, [%4];"
                 : "=r"(r[0]), "=r"(r[1]), "=r"(r[2]), "=r"(r[3]) : "r"(addr));
}

// non-volatile — pure register computation, lets the compiler interleave
static __device__ __forceinline__ void mma_f16(float* d, const uint32_t* a,
                                               uint32_t b0, uint32_t b1) {
    asm("mma.sync.aligned.m16n8k16.row.col.f32.f16.f16.f32 "
        "{%0,%1,%2,%3}, {%4,%5,%6,%7}, {%8,%9}, {%0,%1,%2,%3};"
        : "+f"(d[0]), "+f"(d[1]), "+f"(d[2]), "+f"(d[3])
        : "r"(a[0]), "r"(a[1]), "r"(a[2]), "r"(a[3]), "r"(b0), "r"(b1));
}

static __device__ __forceinline__ void cpasync16(uint32_t dst, const void* src) {
    asm volatile("cp.async.cg.shared.global [%0], [%1], 16;" :: "r"(dst), "l"(src) : "memory");
}

// 64B-row swizzle: physical 16B chunk = logical chunk ^ ((row>>1)&3)
static __device__ __forceinline__ uint32_t row64_addr(uint32_t base, int row, int lchunk) {
    return base + row * 64 + ((lchunk ^ ((row >> 1) & 3)) << 4);
}

// stable strict-> insertion into top-6 (earlier insert wins ties = lower index)
static __device__ __forceinline__ void ins6(float b, float o, int idx,
                                            float* tb, float* to_, int* ti) {
    if (b > tb[KTOP - 1]) {
        int p = KTOP - 1;
#pragma unroll
        for (int q = KTOP - 1; q > 0; q--) {
            if (b > tb[q - 1]) {
                tb[q] = tb[q - 1]; to_[q] = to_[q - 1]; ti[q] = ti[q - 1];
                p = q - 1;
            }
        }
        tb[p] = b; to_[p] = o; ti[p] = idx;
    }
}

// ---------------------------------------------------------------------------
// Pre-kernel: split B[256][4096] fp32 into fp16 hi + scaled lo, stored as the
// exact per-k32-block smem stage image (pre-swizzled 64B rows).
// ---------------------------------------------------------------------------
__global__ __launch_bounds__(256) void preconvert_B(const float* __restrict__ B) {
    int t = blockIdx.x * 256 + threadIdx.x;        // one float4 each; 262144 total
    int n  = t >> 10;                              // row 0..255
    int g  = t & 1023;                             // float4 within row
    int it = g >> 3;                               // k32-block
    int kg = g & 7;                                // float4 within block
    float4 v = *reinterpret_cast<const float4*>(&B[(size_t)n * DDIM + g * 4]);
    uint2 h, l;
    split2_f4(v, h, l);
    int pchunk = (kg >> 1) ^ ((n >> 1) & 3);
    size_t off = (size_t)n * 64 + pchunk * 16 + (kg & 1) * 8;
    size_t base = (size_t)it * 2 * B_LVL;
    *reinterpret_cast<uint2*>(g_bpre + base + 0 * B_LVL + off) = h;
    *reinterpret_cast<uint2*>(g_bpre + base + 1 * B_LVL + off) = l;
}

// ---------------------------------------------------------------------------
// Fused main kernel: fp16x2 HMMA GEMM + sqrt-softplus + stable top-6.
// Key change vs R7: B FRAGMENTS ARE DOUBLE-BUFFERED IN REGISTERS one k16
// step ahead (including across the stage barrier), so ldsm for step k+1
// issues BEFORE the mma batch for step k — the smem crossbar and tensor
// pipe run concurrently instead of alternating in phase.
// acc0 = hi*hi (chunk-folded into smem mst every K=256); acc1 = cross terms
// (scaled 2^11, folded once at the end * 2^-11).
// ---------------------------------------------------------------------------
__global__ __launch_bounds__(NTHREADS, 1) void gate_main(
    const float* __restrict__ A, const float* __restrict__ bias,
    float* __restrict__ out) {
    extern __shared__ char smem[];
    const int tid  = threadIdx.x;
    const int lane = tid & 31;
    const int wid  = tid >> 5;
    const int wm   = wid >> 3;          // 0..1
    const int wn   = wid & 7;           // 0..7
    const int mBase = blockIdx.x * BM;
    float* s_bias = reinterpret_cast<float*>(smem + SM_BIAS);
    float* s_mst  = reinterpret_cast<float*>(smem + SM_MST);

    if (tid < NEXP) s_bias[tid] = bias[tid];

    const int g  = lane >> 3;           // ldmatrix lane group
    const int l7 = lane & 7;

    float acc0[2][4][4], acc1[2][4][4];
#pragma unroll
    for (int mf = 0; mf < 2; mf++)
#pragma unroll
        for (int j = 0; j < 4; j++)
#pragma unroll
            for (int c = 0; c < 4; c++) { acc0[mf][j][c] = 0.0f; acc1[mf][j][c] = 0.0f; }

    // A LDG task: one float4 per thread per stage
    const int arow = tid >> 3;          // 0..63
    const int akg  = tid & 7;
    const int alchunk = akg >> 1, ahalf = (akg & 1) * 8;

    const uint32_t sbase = smem_u32(smem) + SM_STAGE;

    // per-warp fragment row bases
    const int arow0 = wm * 32 + (g & 1) * 8 + l7;          // + mf*16
    const int browf = wn * 32 + (g >> 1) * 8 + l7;         // + nf2*16
    const int lchA  = (g >> 1);                            // + ks*2
    const int lchB  = (g & 1);                             // + ks*2

    // B fragment double buffers: bufA holds even-ks frags, bufB odd-ks
    uint32_t bAh[2][4], bAl[2][4], bBh[2][4], bBl[2][4];

    // ---- prologue: B stages 0,1 via cp.async; A stage 0 ----
#pragma unroll
    for (int s = 0; s < 2; s++) {
        uint32_t st = sbase + s * STAGE_BYTES;
#pragma unroll
        for (int j = 0; j < 4; j++) {
            int idx = j * NTHREADS + tid;
            cpasync16(st + B_OFF + idx * 16,
                      g_bpre + (size_t)s * 2 * B_LVL + idx * 16);
        }
        asm volatile("cp.async.commit_group;" ::: "memory");
    }
    {
        float4 v = *reinterpret_cast<const float4*>(
            &A[(size_t)(mBase + arow) * DDIM + akg * 4]);
        uint2 h, l;
        split2_f4(v, h, l);
        sts_u2(row64_addr(sbase, arow, alchunk) + ahalf, h);
        sts_u2(row64_addr(sbase + A_LVL, arow, alchunk) + ahalf, l);
    }
    asm volatile("cp.async.wait_group 1;" ::: "memory");
    __syncthreads();
    // preload bufA <- (stage 0, ks0)
#pragma unroll
    for (int nf2 = 0; nf2 < 2; nf2++) {
        ldsm4(bAh[nf2], row64_addr(sbase + B_OFF, browf + nf2 * 16, lchB));
        ldsm4(bAl[nf2], row64_addr(sbase + B_OFF + B_LVL, browf + nf2 * 16, lchB));
    }

#pragma unroll 1
    for (int it = 0; it < NIT; it++) {
        const uint32_t stage  = sbase + (it % 3) * STAGE_BYTES;
        const uint32_t nstage = sbase + ((it + 1) % 3) * STAGE_BYTES;

        // prefetch B(it+2) smem + A(it+1) regs
        float4 areg;
        if (it + 2 < NIT) {
            const uint32_t n2stage = sbase + ((it + 2) % 3) * STAGE_BYTES;
#pragma unroll
            for (int j = 0; j < 4; j++) {
                int idx = j * NTHREADS + tid;
                cpasync16(n2stage + B_OFF + idx * 16,
                          g_bpre + (size_t)(it + 2) * 2 * B_LVL + idx * 16);
            }
            asm volatile("cp.async.commit_group;" ::: "memory");
        }
        if (it + 1 < NIT) {
            areg = *reinterpret_cast<const float4*>(
                &A[(size_t)(mBase + arow) * DDIM + (it + 1) * BK + akg * 4]);
        }

        // ======== k16 step 0: mma uses bufA; ldsm ks1 into bufB FIRST ======
        uint32_t ah[2][4], al[2][4];
#pragma unroll
        for (int mf = 0; mf < 2; mf++) {
            ldsm4(ah[mf], row64_addr(stage, arow0 + mf * 16, lchA));
            ldsm4(al[mf], row64_addr(stage + A_LVL, arow0 + mf * 16, lchA));
        }
#pragma unroll
        for (int nf2 = 0; nf2 < 2; nf2++) {
            ldsm4(bBh[nf2], row64_addr(stage + B_OFF, browf + nf2 * 16, 2 + lchB));
            ldsm4(bBl[nf2], row64_addr(stage + B_OFF + B_LVL, browf + nf2 * 16, 2 + lchB));
        }
        // pass 1: ah*bh (acc0), ah*bl (acc1)
#pragma unroll
        for (int nf2 = 0; nf2 < 2; nf2++)
#pragma unroll
            for (int mf = 0; mf < 2; mf++) {
                mma_f16(acc0[mf][nf2 * 2 + 0], ah[mf], bAh[nf2][0], bAh[nf2][1]);
                mma_f16(acc0[mf][nf2 * 2 + 1], ah[mf], bAh[nf2][2], bAh[nf2][3]);
                mma_f16(acc1[mf][nf2 * 2 + 0], ah[mf], bAl[nf2][0], bAl[nf2][1]);
                mma_f16(acc1[mf][nf2 * 2 + 1], ah[mf], bAl[nf2][2], bAl[nf2][3]);
            }
        // pass 2: al*bh (acc1)
#pragma unroll
        for (int nf2 = 0; nf2 < 2; nf2++)
#pragma unroll
            for (int mf = 0; mf < 2; mf++) {
                mma_f16(acc1[mf][nf2 * 2 + 0], al[mf], bAh[nf2][0], bAh[nf2][1]);
                mma_f16(acc1[mf][nf2 * 2 + 1], al[mf], bAh[nf2][2], bAh[nf2][3]);
            }

        // ======== k16 step 1: mma uses bufB; A ldsm + STS fill the gap =====
#pragma unroll
        for (int mf = 0; mf < 2; mf++) {
            ldsm4(ah[mf], row64_addr(stage, arow0 + mf * 16, 2 + lchA));
            ldsm4(al[mf], row64_addr(stage + A_LVL, arow0 + mf * 16, 2 + lchA));
        }
        if (it + 1 < NIT) {
            uint2 h, l;
            split2_f4(areg, h, l);
            sts_u2(row64_addr(nstage, arow, alchunk) + ahalf, h);
            sts_u2(row64_addr(nstage + A_LVL, arow, alchunk) + ahalf, l);
        }
#pragma unroll
        for (int nf2 = 0; nf2 < 2; nf2++)
#pragma unroll
            for (int mf = 0; mf < 2; mf++) {
                mma_f16(acc0[mf][nf2 * 2 + 0], ah[mf], bBh[nf2][0], bBh[nf2][1]);
                mma_f16(acc0[mf][nf2 * 2 + 1], ah[mf], bBh[nf2][2], bBh[nf2][3]);
                mma_f16(acc1[mf][nf2 * 2 + 0], ah[mf], bBl[nf2][0], bBl[nf2][1]);
                mma_f16(acc1[mf][nf2 * 2 + 1], ah[mf], bBl[nf2][2], bBl[nf2][3]);
            }
#pragma unroll
        for (int nf2 = 0; nf2 < 2; nf2++)
#pragma unroll
            for (int mf = 0; mf < 2; mf++) {
                mma_f16(acc1[mf][nf2 * 2 + 0], al[mf], bBh[nf2][0], bBh[nf2][1]);
                mma_f16(acc1[mf][nf2 * 2 + 1], al[mf], bBh[nf2][2], bBh[nf2][3]);
            }

        // ======== cross-stage: preload bufA <- (it+1, ks0) pre-barrier =====
        if (it + 1 < NIT) {
            if (it + 2 < NIT) {
                asm volatile("cp.async.wait_group 1;" ::: "memory");
            } else {
                asm volatile("cp.async.wait_group 0;" ::: "memory");
            }
#pragma unroll
            for (int nf2 = 0; nf2 < 2; nf2++) {
                ldsm4(bAh[nf2], row64_addr(nstage + B_OFF, browf + nf2 * 16, lchB));
                ldsm4(bAl[nf2], row64_addr(nstage + B_OFF + B_LVL, browf + nf2 * 16, lchB));
            }
        }

        // fold hi*hi chunk into smem master every 8 iterations (K chunk = 256)
        if ((it & 7) == 7) {
            if (it == 7) {
#pragma unroll
                for (int mf = 0; mf < 2; mf++)
#pragma unroll
                    for (int j = 0; j < 4; j++)
#pragma unroll
                        for (int c = 0; c < 4; c++) {
                            s_mst[((mf * 4 + j) * 4 + c) * NTHREADS + tid] = acc0[mf][j][c];
                            acc0[mf][j][c] = 0.0f;
                        }
            } else {
#pragma unroll
                for (int mf = 0; mf < 2; mf++)
#pragma unroll
                    for (int j = 0; j < 4; j++)
#pragma unroll
                        for (int c = 0; c < 4; c++) {
                            s_mst[((mf * 4 + j) * 4 + c) * NTHREADS + tid] += acc0[mf][j][c];
                            acc0[mf][j][c] = 0.0f;
                        }
            }
        }

        __syncthreads();
    }

    // ---- write scores to smem (overlay stages): score = mst + acc1 * 2^-11 ----
    float* sc = reinterpret_cast<float*>(smem + SM_SCORES);
#pragma unroll
    for (int mf = 0; mf < 2; mf++) {
#pragma unroll
        for (int nf = 0; nf < 4; nf++) {
            int m0 = wm * 32 + mf * 16 + (lane >> 2);
            int n0 = wn * 32 + nf * 8 + (lane & 3) * 2;
            int jb = (mf * 4 + nf) * 4;
            float s0 = s_mst[(jb + 0) * NTHREADS + tid] + acc1[mf][nf][0] * LO_UNSCALE;
            float s1 = s_mst[(jb + 1) * NTHREADS + tid] + acc1[mf][nf][1] * LO_UNSCALE;
            float s2 = s_mst[(jb + 2) * NTHREADS + tid] + acc1[mf][nf][2] * LO_UNSCALE;
            float s3 = s_mst[(jb + 3) * NTHREADS + tid] + acc1[mf][nf][3] * LO_UNSCALE;
            *reinterpret_cast<float2*>(&sc[m0 * SSTR + n0]) = make_float2(s0, s1);
            *reinterpret_cast<float2*>(&sc[(m0 + 8) * SSTR + n0]) = make_float2(s2, s3);
        }
    }
    __syncthreads();

    // ---- top-6: 8 threads per row, each scans 32 experts, then merge ----
    {
        const int r = tid >> 3;     // row 0..63
        const int q = tid & 7;      // eighth
        float tb[KTOP], to_[KTOP];
        int ti[KTOP];
#pragma unroll
        for (int i = 0; i < KTOP; i++) { tb[i] = -1e30f; to_[i] = 0.0f; ti[i] = 0; }
#pragma unroll 4
        for (int j = 0; j < 32; j++) {
            int e = q * 32 + j;
            float z = sc[r * SSTR + e];
            float sp = fmaxf(z, 0.0f) + log1pf(expf(-fabsf(z)));
            float o = sqrtf(sp);
            ins6(o + s_bias[e], o, e, tb, to_, ti);
        }
        float* pb = reinterpret_cast<float*>(smem + SM_PB);
        float* po = reinterpret_cast<float*>(smem + SM_PO);
        int*   pi = reinterpret_cast<int*>(smem + SM_PI);
#pragma unroll
        for (int i = 0; i < KTOP; i++) {
            pb[(r * 8 + q) * KTOP + i] = tb[i];
            po[(r * 8 + q) * KTOP + i] = to_[i];
            pi[(r * 8 + q) * KTOP + i] = ti[i];
        }
        __syncthreads();

        if (q == 0) {
            float fb[KTOP], fo[KTOP];
            int fi[KTOP];
#pragma unroll
            for (int i = 0; i < KTOP; i++) { fb[i] = -1e30f; fo[i] = 0.0f; fi[i] = 0; }
#pragma unroll
            for (int q2 = 0; q2 < 8; q2++)
#pragma unroll
                for (int i = 0; i < KTOP; i++)
                    ins6(pb[(r * 8 + q2) * KTOP + i], po[(r * 8 + q2) * KTOP + i],
                         pi[(r * 8 + q2) * KTOP + i], fb, fo, fi);
            float sum = 0.0f;
#pragma unroll
            for (int i = 0; i < KTOP; i++) sum += fo[i];
            const float s = 1.5f / sum;
            const size_t row = (size_t)(mBase + r);
#pragma unroll
            for (int i = 0; i < KTOP; i++) {
                out[row * KTOP + i] = fo[i] * s;
                out[(size_t)N_ROWS * KTOP + row * KTOP + i] = (float)fi[i];
            }
        }
    }
}

extern "C" void kernel_launch(void* const* d_in, const int* in_sizes, int n_in,
                              void* d_out, int out_size) {
    const float* x      = (const float*)d_in[0];   // [N, D]
    const float* weight = (const float*)d_in[1];   // [E, D]
    const float* bias   = (const float*)d_in[2];   // [E]
    float* out = (float*)d_out;

    preconvert_B<<<(NEXP * DDIM / 4) / 256, 256>>>(weight);
    cudaFuncSetAttribute(gate_main, cudaFuncAttributeMaxDynamicSharedMemorySize, SMEM_TOTAL);
    gate_main<<<N_ROWS / BM, NTHREADS, SMEM_TOTAL>>>(x, bias, out);
}

// round 12
// speedup vs baseline: 1.0981x; 1.0669x over previous
#include <cuda_runtime.h>
#include <cuda_fp16.h>
#include <cstdint>
#include <math.h>

#define N_ROWS 16384
#define DDIM   4096
#define NEXP   256
#define KTOP   6

#define BM 64             // rows per CTA
#define BK 32             // k per stage (two k16 steps)
#define NIT (DDIM / BK)   // 128
#define NTHREADS 256      // 8 warps: 2 (m) x 4 (n), warp tile 32x64
#define LO_SCALE 2048.0f
#define LO_UNSCALE 4.8828125e-4f   // 2^-11

// ---- smem layout (dynamic) ----
// [0,1024): bias; 2 stages at 1024 + s*40960; masters after stages
// stage: A_h 4K | A_l 4K | B_h 16K | B_l 16K = 40K
#define SM_BIAS    0
#define SM_STAGE   1024
#define STAGE_BYTES 40960
#define A_LVL 4096
#define B_OFF 8192
#define B_LVL 16384
#define SM_MST     (SM_STAGE + 2 * STAGE_BYTES)            // 82944
#define SMEM_TOTAL (SM_MST + 64 * NTHREADS * 4)            // 148480

// scores overlay (after mainloop, over stage region)
#define SSTR 260
#define SM_SCORES  SM_STAGE
#define SM_PB (SM_SCORES + BM * SSTR * 4)                  // 67584
#define SM_PO (SM_PB + BM * 4 * KTOP * 4)
#define SM_PI (SM_PO + BM * 4 * KTOP * 4)

// 4 MB pre-converted, pre-swizzled B: [k32-block(128)][level(2)][n(256)][64B]
__device__ __align__(16) uint8_t g_bpre[(size_t)128 * 2 * NEXP * 64];

// ---------------------------------------------------------------------------
static __device__ __forceinline__ uint32_t smem_u32(const void* p) {
    uint32_t a;
    asm("{ .reg .u64 t; cvta.to.shared.u64 t, %1; cvt.u32.u64 %0, t; }" : "=r"(a) : "l"(p));
    return a;
}

static __device__ __forceinline__ void sts_u2(uint32_t addr, uint2 v) {
    asm volatile("st.shared.v2.b32 [%0], {%1, %2};"
                 :: "r"(addr), "r"(v.x), "r"(v.y) : "memory");
}

static __device__ __forceinline__ uint32_t pack_h2(__half lo, __half hi) {
    return (uint32_t)__half_as_ushort(lo) | ((uint32_t)__half_as_ushort(hi) << 16);
}

// split fp32x4 into fp16 hi + fp16 lo*2^11 (lo pre-scaled into normal range)
static __device__ __forceinline__ void split2_f4(float4 v, uint2& h, uint2& l) {
    float in[4] = {v.x, v.y, v.z, v.w};
    __half hh[4], hl[4];
#pragma unroll
    for (int i = 0; i < 4; i++) {
        float a = in[i];
        hh[i] = __float2half_rn(a);
        float r = a - __half2float(hh[i]);
        hl[i] = __float2half_rn(r * LO_SCALE);
    }
    h = make_uint2(pack_h2(hh[0], hh[1]), pack_h2(hh[2], hh[3]));
    l = make_uint2(pack_h2(hl[0], hl[1]), pack_h2(hl[2], hl[3]));
}

static __device__ __forceinline__ void ldsm4(uint32_t* r, uint32_t addr) {
    asm volatile("ldmatrix.sync.aligned.m8n8.x4.shared.b16 {%0,%1,%2,%3}, [%4];"
                 : "=r"(r[0]), "=r"(r[1]), "=r"(r[2]), "=r"(r[3]) : "r"(addr));
}

// non-volatile — pure register computation, lets the compiler interleave
static __device__ __forceinline__ void mma_f16(float* d, const uint32_t* a,
                                               uint32_t b0, uint32_t b1) {
    asm("mma.sync.aligned.m16n8k16.row.col.f32.f16.f16.f32 "
        "{%0,%1,%2,%3}, {%4,%5,%6,%7}, {%8,%9}, {%0,%1,%2,%3};"
        : "+f"(d[0]), "+f"(d[1]), "+f"(d[2]), "+f"(d[3])
        : "r"(a[0]), "r"(a[1]), "r"(a[2]), "r"(a[3]), "r"(b0), "r"(b1));
}

static __device__ __forceinline__ void cpasync16(uint32_t dst, const void* src) {
    asm volatile("cp.async.cg.shared.global [%0], [%1], 16;" :: "r"(dst), "l"(src) : "memory");
}

// 64B-row swizzle: physical 16B chunk = logical chunk ^ ((row>>1)&3)
static __device__ __forceinline__ uint32_t row64_addr(uint32_t base, int row, int lchunk) {
    return base + row * 64 + ((lchunk ^ ((row >> 1) & 3)) << 4);
}

// stable strict-> insertion into top-6 (earlier insert wins ties = lower index)
static __device__ __forceinline__ void ins6(float b, float o, int idx,
                                            float* tb, float* to_, int* ti) {
    if (b > tb[KTOP - 1]) {
        int p = KTOP - 1;
#pragma unroll
        for (int q = KTOP - 1; q > 0; q--) {
            if (b > tb[q - 1]) {
                tb[q] = tb[q - 1]; to_[q] = to_[q - 1]; ti[q] = ti[q - 1];
                p = q - 1;
            }
        }
        tb[p] = b; to_[p] = o; ti[p] = idx;
    }
}

// ---------------------------------------------------------------------------
// Pre-kernel: split B[256][4096] fp32 into fp16 hi + scaled lo, stored as the
// exact per-k32-block smem stage image (pre-swizzled 64B rows).
// ---------------------------------------------------------------------------
__global__ __launch_bounds__(256) void preconvert_B(const float* __restrict__ B) {
    int t = blockIdx.x * 256 + threadIdx.x;        // one float4 each; 262144 total
    int n  = t >> 10;                              // row 0..255
    int g  = t & 1023;                             // float4 within row
    int it = g >> 3;                               // k32-block
    int kg = g & 7;                                // float4 within block
    float4 v = *reinterpret_cast<const float4*>(&B[(size_t)n * DDIM + g * 4]);
    uint2 h, l;
    split2_f4(v, h, l);
    int pchunk = (kg >> 1) ^ ((n >> 1) & 3);
    size_t off = (size_t)n * 64 + pchunk * 16 + (kg & 1) * 8;
    size_t base = (size_t)it * 2 * B_LVL;
    *reinterpret_cast<uint2*>(g_bpre + base + 0 * B_LVL + off) = h;
    *reinterpret_cast<uint2*>(g_bpre + base + 1 * B_LVL + off) = l;
}

// ---------------------------------------------------------------------------
// Fused main kernel: fp16x2 HMMA GEMM + sqrt-softplus + stable top-6.
// R5's REGIME: 8 warps, warp tile 32x64, all operands via smem + ldsm,
// 2-stage cp.async ping-pong, register accumulators (masters in smem).
// Per warp-k16: 12 ldsm feed 48 MMAs. acc0 = hi*hi (folded into smem masters
// every K=256); acc1 = cross terms (scaled 2^11, folded once * 2^-11).
// ---------------------------------------------------------------------------
__global__ __launch_bounds__(NTHREADS, 1) void gate_main(
    const float* __restrict__ A, const float* __restrict__ bias,
    float* __restrict__ out) {
    extern __shared__ char smem[];
    const int tid  = threadIdx.x;
    const int lane = tid & 31;
    const int wid  = tid >> 5;
    const int wm   = wid >> 2;          // 0..1
    const int wn   = wid & 3;           // 0..3
    const int mBase = blockIdx.x * BM;
    float* s_bias = reinterpret_cast<float*>(smem + SM_BIAS);
    float* s_mst  = reinterpret_cast<float*>(smem + SM_MST);

    if (tid < NEXP) s_bias[tid] = bias[tid];

    const int g  = lane >> 3;           // ldmatrix lane group
    const int l7 = lane & 7;

    float acc0[2][8][4], acc1[2][8][4];
#pragma unroll
    for (int mf = 0; mf < 2; mf++)
#pragma unroll
        for (int j = 0; j < 8; j++)
#pragma unroll
            for (int c = 0; c < 4; c++) { acc0[mf][j][c] = 0.0f; acc1[mf][j][c] = 0.0f; }

    const uint32_t sbase = smem_u32(smem) + SM_STAGE;

    // ---- prologue: B stage 0 via cp.async, A stage 0 via LDG+split+STS ----
    {
#pragma unroll
        for (int j = 0; j < 8; j++) {
            int idx = j * NTHREADS + tid;
            cpasync16(sbase + B_OFF + idx * 16, g_bpre + idx * 16);
        }
        asm volatile("cp.async.commit_group;" ::: "memory");
#pragma unroll
        for (int s = 0; s < 2; s++) {
            int task = s * NTHREADS + tid;
            int row = task >> 3, kg = task & 7;
            float4 v = *reinterpret_cast<const float4*>(
                &A[(size_t)(mBase + row) * DDIM + kg * 4]);
            uint2 h, l;
            split2_f4(v, h, l);
            int lchunk = kg >> 1, half = (kg & 1) * 8;
            sts_u2(row64_addr(sbase, row, lchunk) + half, h);
            sts_u2(row64_addr(sbase + A_LVL, row, lchunk) + half, l);
        }
        asm volatile("cp.async.wait_group 0;" ::: "memory");
        __syncthreads();
    }

#pragma unroll 1
    for (int it = 0; it < NIT; it++) {
        const uint32_t stage  = sbase + (it & 1) * STAGE_BYTES;
        const uint32_t nstage = sbase + ((it + 1) & 1) * STAGE_BYTES;

        float4 areg[2];
        if (it + 1 < NIT) {
#pragma unroll
            for (int j = 0; j < 8; j++) {
                int idx = j * NTHREADS + tid;
                cpasync16(nstage + B_OFF + idx * 16,
                          g_bpre + (size_t)(it + 1) * 2 * B_LVL + idx * 16);
            }
            asm volatile("cp.async.commit_group;" ::: "memory");
#pragma unroll
            for (int s = 0; s < 2; s++) {
                int task = s * NTHREADS + tid;
                int row = task >> 3, kg = task & 7;
                areg[s] = *reinterpret_cast<const float4*>(
                    &A[(size_t)(mBase + row) * DDIM + (it + 1) * BK + kg * 4]);
            }
        }

        // ---- compute current stage: 2 k16 steps, warp tile 32x64 ----
#pragma unroll
        for (int ks = 0; ks < 2; ks++) {
            uint32_t ah[2][4], al[2][4];
#pragma unroll
            for (int mf = 0; mf < 2; mf++) {
                int row = wm * 32 + mf * 16 + (g & 1) * 8 + l7;
                int lchunk = ks * 2 + (g >> 1);
                ldsm4(ah[mf], row64_addr(stage, row, lchunk));
                ldsm4(al[mf], row64_addr(stage + A_LVL, row, lchunk));
            }
            int lchb = ks * 2 + (g & 1);
#pragma unroll
            for (int nf2 = 0; nf2 < 4; nf2++) {
                int rowb = wn * 64 + nf2 * 16 + (g >> 1) * 8 + l7;
                uint32_t bh[4], bl[4];
                ldsm4(bh, row64_addr(stage + B_OFF, rowb, lchb));
                ldsm4(bl, row64_addr(stage + B_OFF + B_LVL, rowb, lchb));
#pragma unroll
                for (int mf = 0; mf < 2; mf++) {
                    mma_f16(acc0[mf][nf2 * 2 + 0], ah[mf], bh[0], bh[1]);
                    mma_f16(acc0[mf][nf2 * 2 + 1], ah[mf], bh[2], bh[3]);
                    mma_f16(acc1[mf][nf2 * 2 + 0], ah[mf], bl[0], bl[1]);
                    mma_f16(acc1[mf][nf2 * 2 + 1], ah[mf], bl[2], bl[3]);
                    mma_f16(acc1[mf][nf2 * 2 + 0], al[mf], bh[0], bh[1]);
                    mma_f16(acc1[mf][nf2 * 2 + 1], al[mf], bh[2], bh[3]);
                }
            }
        }

        if (it + 1 < NIT) {
#pragma unroll
            for (int s = 0; s < 2; s++) {
                int task = s * NTHREADS + tid;
                int row = task >> 3, kg = task & 7;
                uint2 h, l;
                split2_f4(areg[s], h, l);
                int lchunk = kg >> 1, half = (kg & 1) * 8;
                sts_u2(row64_addr(nstage, row, lchunk) + half, h);
                sts_u2(row64_addr(nstage + A_LVL, row, lchunk) + half, l);
            }
        }

        // fold hi*hi chunk into smem masters every 8 iterations (K chunk = 256)
        if ((it & 7) == 7) {
            if (it == 7) {
#pragma unroll
                for (int mf = 0; mf < 2; mf++)
#pragma unroll
                    for (int j = 0; j < 8; j++)
#pragma unroll
                        for (int c = 0; c < 4; c++) {
                            s_mst[((mf * 8 + j) * 4 + c) * NTHREADS + tid] = acc0[mf][j][c];
                            acc0[mf][j][c] = 0.0f;
                        }
            } else {
#pragma unroll
                for (int mf = 0; mf < 2; mf++)
#pragma unroll
                    for (int j = 0; j < 8; j++)
#pragma unroll
                        for (int c = 0; c < 4; c++) {
                            s_mst[((mf * 8 + j) * 4 + c) * NTHREADS + tid] += acc0[mf][j][c];
                            acc0[mf][j][c] = 0.0f;
                        }
            }
        }

        if (it + 1 < NIT)
            asm volatile("cp.async.wait_group 0;" ::: "memory");
        __syncthreads();
    }

    // ---- write scores to smem (overlay stages): score = mst + acc1 * 2^-11 ----
    float* sc = reinterpret_cast<float*>(smem + SM_SCORES);
#pragma unroll
    for (int mf = 0; mf < 2; mf++) {
#pragma unroll
        for (int nf = 0; nf < 8; nf++) {
            int m0 = wm * 32 + mf * 16 + (lane >> 2);
            int n0 = wn * 64 + nf * 8 + (lane & 3) * 2;
            int jb = (mf * 8 + nf) * 4;
            float s0 = s_mst[(jb + 0) * NTHREADS + tid] + acc1[mf][nf][0] * LO_UNSCALE;
            float s1 = s_mst[(jb + 1) * NTHREADS + tid] + acc1[mf][nf][1] * LO_UNSCALE;
            float s2 = s_mst[(jb + 2) * NTHREADS + tid] + acc1[mf][nf][2] * LO_UNSCALE;
            float s3 = s_mst[(jb + 3) * NTHREADS + tid] + acc1[mf][nf][3] * LO_UNSCALE;
            *reinterpret_cast<float2*>(&sc[m0 * SSTR + n0]) = make_float2(s0, s1);
            *reinterpret_cast<float2*>(&sc[(m0 + 8) * SSTR + n0]) = make_float2(s2, s3);
        }
    }
    __syncthreads();

    // ---- top-6: 4 threads per row, each scans 64 experts, then merge ----
    {
        const int r = tid >> 2;     // row 0..63
        const int q = tid & 3;      // quarter
        float tb[KTOP], to_[KTOP];
        int ti[KTOP];
#pragma unroll
        for (int i = 0; i < KTOP; i++) { tb[i] = -1e30f; to_[i] = 0.0f; ti[i] = 0; }
#pragma unroll 4
        for (int j = 0; j < 64; j++) {
            int e = q * 64 + j;
            float z = sc[r * SSTR + e];
            float sp = fmaxf(z, 0.0f) + log1pf(expf(-fabsf(z)));
            float o = sqrtf(sp);
            ins6(o + s_bias[e], o, e, tb, to_, ti);
        }
        float* pb = reinterpret_cast<float*>(smem + SM_PB);
        float* po = reinterpret_cast<float*>(smem + SM_PO);
        int*   pi = reinterpret_cast<int*>(smem + SM_PI);
#pragma unroll
        for (int i = 0; i < KTOP; i++) {
            pb[(r * 4 + q) * KTOP + i] = tb[i];
            po[(r * 4 + q) * KTOP + i] = to_[i];
            pi[(r * 4 + q) * KTOP + i] = ti[i];
        }
        __syncthreads();

        if (q == 0) {
            float fb[KTOP], fo[KTOP];
            int fi[KTOP];
#pragma unroll
            for (int i = 0; i < KTOP; i++) { fb[i] = -1e30f; fo[i] = 0.0f; fi[i] = 0; }
#pragma unroll
            for (int q2 = 0; q2 < 4; q2++)
#pragma unroll
                for (int i = 0; i < KTOP; i++)
                    ins6(pb[(r * 4 + q2) * KTOP + i], po[(r * 4 + q2) * KTOP + i],
                         pi[(r * 4 + q2) * KTOP + i], fb, fo, fi);
            float sum = 0.0f;
#pragma unroll
            for (int i = 0; i < KTOP; i++) sum += fo[i];
            const float s = 1.5f / sum;
            const size_t row = (size_t)(mBase + r);
#pragma unroll
            for (int i = 0; i < KTOP; i++) {
                out[row * KTOP + i] = fo[i] * s;
                out[(size_t)N_ROWS * KTOP + row * KTOP + i] = (float)fi[i];
            }
        }
    }
}

extern "C" void kernel_launch(void* const* d_in, const int* in_sizes, int n_in,
                              void* d_out, int out_size) {
    const float* x      = (const float*)d_in[0];   // [N, D]
    const float* weight = (const float*)d_in[1];   // [E, D]
    const float* bias   = (const float*)d_in[2];   // [E]
    float* out = (float*)d_out;

    preconvert_B<<<(NEXP * DDIM / 4) / 256, 256>>>(weight);
    cudaFuncSetAttribute(gate_main, cudaFuncAttributeMaxDynamicSharedMemorySize, SMEM_TOTAL);
    gate_main<<<N_ROWS / BM, NTHREADS, SMEM_TOTAL>>>(x, bias, out);
}